// round 15
// baseline (speedup 1.0000x reference)
#include <cuda_runtime.h>
#include <cuda_bf16.h>
#include <cstdint>

// Problem constants
#define B_  64
#define C_  3
#define H_  224
#define W_  224
#define GH  28
#define GW  28
#define D_  768
#define KD  192                 // C*8*8
#define M_  (B_*GH*GW)          // 50176

#define PX 1176                 // x: 2408448 float4 / (1176*256) = 8 per thread
#define PW 36                   // w: 36864 float4 / (36*256) = 4 per thread

// ---- scratch (no cudaMalloc allowed) ----
__device__ float g_partials[PX + PW];
__device__ float g_scales[3];                              // sx, sw, sx*sw
__device__ int   g_count = 0;                              // self-resetting
__device__ __nv_bfloat16 g_xq[(size_t)M_ * KD];            // 19.3 MB
__device__ __nv_bfloat16 g_wq[(size_t)D_ * KD];            // 288 KB

// ===========================================================================
// Pass 1: per-block absmax partials (8 independent LDG.128 per thread)
// + fused last-block scale reduction
// ===========================================================================
__device__ __forceinline__ float amax4(float4 v) {
    return fmaxf(fmaxf(fabsf(v.x), fabsf(v.y)), fmaxf(fabsf(v.z), fabsf(v.w)));
}

__global__ void absmax_kernel(const float4* __restrict__ x4,
                              const float4* __restrict__ w4) {
    __shared__ float red[8];
    __shared__ int is_last;
    float m = 0.f;
    if (blockIdx.x < PX) {
        // 8 fully independent loads, stride PX*256 float4s
        int i = blockIdx.x * 256 + threadIdx.x;
        const int st = PX * 256;
        float4 v0 = x4[i];
        float4 v1 = x4[i + st];
        float4 v2 = x4[i + 2 * st];
        float4 v3 = x4[i + 3 * st];
        float4 v4 = x4[i + 4 * st];
        float4 v5 = x4[i + 5 * st];
        float4 v6 = x4[i + 6 * st];
        float4 v7 = x4[i + 7 * st];
        m = fmaxf(fmaxf(fmaxf(amax4(v0), amax4(v1)), fmaxf(amax4(v2), amax4(v3))),
                  fmaxf(fmaxf(amax4(v4), amax4(v5)), fmaxf(amax4(v6), amax4(v7))));
    } else {
        int i = (blockIdx.x - PX) * 256 + threadIdx.x;
        const int st = PW * 256;
        float4 v0 = w4[i];
        float4 v1 = w4[i + st];
        float4 v2 = w4[i + 2 * st];
        float4 v3 = w4[i + 3 * st];
        m = fmaxf(fmaxf(amax4(v0), amax4(v1)), fmaxf(amax4(v2), amax4(v3)));
    }
#pragma unroll
    for (int o = 16; o > 0; o >>= 1)
        m = fmaxf(m, __shfl_xor_sync(0xffffffffu, m, o));
    if ((threadIdx.x & 31) == 0) red[threadIdx.x >> 5] = m;
    __syncthreads();
    if (threadIdx.x < 32) {
        float v = (threadIdx.x < 8) ? red[threadIdx.x] : 0.f;
#pragma unroll
        for (int o = 4; o > 0; o >>= 1)
            v = fmaxf(v, __shfl_xor_sync(0xffffffffu, v, o));
        if (threadIdx.x == 0) {
            g_partials[blockIdx.x] = v;
            __threadfence();
            int c = atomicAdd(&g_count, 1);
            is_last = (c == PX + PW - 1);
        }
    }
    __syncthreads();
    if (!is_last) return;

    float xv = 0.f, wv = 0.f;
    for (int j = threadIdx.x; j < PX; j += 256) xv = fmaxf(xv, g_partials[j]);
    if (threadIdx.x < PW) wv = g_partials[PX + threadIdx.x];
#pragma unroll
    for (int o = 16; o > 0; o >>= 1) {
        xv = fmaxf(xv, __shfl_xor_sync(0xffffffffu, xv, o));
        wv = fmaxf(wv, __shfl_xor_sync(0xffffffffu, wv, o));
    }
    __shared__ float rx[8], rw[8];
    if ((threadIdx.x & 31) == 0) {
        rx[threadIdx.x >> 5] = xv;
        rw[threadIdx.x >> 5] = wv;
    }
    __syncthreads();
    if (threadIdx.x == 0) {
        float a = rx[0], b = rw[0];
#pragma unroll
        for (int j = 1; j < 8; j++) {
            a = fmaxf(a, rx[j]);
            b = fmaxf(b, rw[j]);
        }
        float sx = fmaxf(a, 1e-8f) / 127.0f;
        float sw = fmaxf(b, 1e-8f) / 127.0f;
        g_scales[0] = sx;
        g_scales[1] = sw;
        g_scales[2] = sx * sw;
        g_count = 0;   // reset for next graph replay
    }
}

// ===========================================================================
// Pass 2: quantize w (copy) + x (patchify) -> bf16, one launch, coalesced
// ===========================================================================
__device__ __forceinline__ float fq(float v, float s) {
    return rintf(fminf(fmaxf(v / s, -127.f), 127.f));
}
__device__ __forceinline__ unsigned int pack2(float a, float b, float s) {
    __nv_bfloat162 h = __floats2bfloat162_rn(fq(a, s), fq(b, s));
    return *reinterpret_cast<unsigned int*>(&h);
}

#define WQBLOCKS 144   // 144*256 = 36864 = D_*KD/4
#define XQBLOCKS 4704  // 4704*256 = 1204224 = B_*C_*H_*GW

__global__ void quant_kernel(const float* __restrict__ x,
                             const float* __restrict__ w) {
    int bid = blockIdx.x;
    if (bid < WQBLOCKS) {
        float s = g_scales[1];
        int i = bid * 256 + threadIdx.x;
        float4 v = reinterpret_cast<const float4*>(w)[i];
        uint2 o;
        o.x = pack2(v.x, v.y, s);
        o.y = pack2(v.z, v.w, s);
        reinterpret_cast<uint2*>(g_wq)[i] = o;
    } else {
        float s = g_scales[0];
        int tid = (bid - WQBLOCKS) * 256 + threadIdx.x;
        int wb = tid % GW;
        int h  = (tid / GW) % H_;
        int c  = (tid / (GW * H_)) % C_;
        int b  = tid / (GW * H_ * C_);
        const float4* src = reinterpret_cast<const float4*>(
            x + ((((size_t)b * C_ + c) * H_ + h) * W_ + (size_t)wb * 8));
        float4 v0 = src[0], v1 = src[1];
        int xb = h >> 3, p = h & 7;
        size_t m = (size_t)b * (GH * GW) + (size_t)xb * GW + wb;
        size_t k = (size_t)c * 64 + (size_t)p * 8;
        uint4 o;
        o.x = pack2(v0.x, v0.y, s);
        o.y = pack2(v0.z, v0.w, s);
        o.z = pack2(v1.x, v1.y, s);
        o.w = pack2(v1.z, v1.w, s);
        *reinterpret_cast<uint4*>(g_xq + m * KD + k) = o;
    }
}

// ===========================================================================
// Pass 3: GEMM. 128 threads, 4 warps, warp tile 64x64 (2x2): smem fragment
// traffic 192KB/tile (vs 288KB at 4x2) -> smem-BW bound lifted. Fragment
// double-buffering hides LDSM latency at 2 warps/SMSP. T=2 bn tiles per CTA
// (grid (3,392)); next-B cp.async overlaps epilogue.
// ===========================================================================
#define SSTRIDE 200                      // bf16 elems per smem row (400 B)
#define A_OFF   0
#define B_OFF   (128 * SSTRIDE * 2)      // 51200 B
#define BIAS_OFF (2 * 128 * SSTRIDE * 2) // 102400 B
#define GEMM_SMEM (BIAS_OFF + 1024)

__device__ __forceinline__ uint32_t smem_u32(const void* p) {
    uint32_t a;
    asm("{ .reg .u64 t; cvta.to.shared.u64 t, %1; cvt.u32.u64 %0, t; }"
        : "=r"(a) : "l"(p));
    return a;
}
__device__ __forceinline__ void cp16(uint32_t dst, const void* src) {
    asm volatile("cp.async.cg.shared.global [%0], [%1], 16;"
                 :: "r"(dst), "l"(src));
}
__device__ __forceinline__ void cp_commit() {
    asm volatile("cp.async.commit_group;" ::: "memory");
}
__device__ __forceinline__ void cp_wait0() {
    asm volatile("cp.async.wait_group 0;" ::: "memory");
}
__device__ __forceinline__ void ldsm4(uint32_t* r, uint32_t addr) {
    asm volatile("ldmatrix.sync.aligned.m8n8.x4.shared.b16 {%0,%1,%2,%3}, [%4];"
                 : "=r"(r[0]), "=r"(r[1]), "=r"(r[2]), "=r"(r[3]) : "r"(addr));
}
__device__ __forceinline__ void mma16816(float* d, const uint32_t* a,
                                         uint32_t b0, uint32_t b1) {
    asm volatile(
        "mma.sync.aligned.m16n8k16.row.col.f32.bf16.bf16.f32 "
        "{%0,%1,%2,%3}, {%4,%5,%6,%7}, {%8,%9}, {%0,%1,%2,%3};\n"
        : "+f"(d[0]), "+f"(d[1]), "+f"(d[2]), "+f"(d[3])
        : "r"(a[0]), "r"(a[1]), "r"(a[2]), "r"(a[3]), "r"(b0), "r"(b1));
}

__global__ void __launch_bounds__(128, 2)
gemm_kernel(const float* __restrict__ bias, float* __restrict__ out) {
    extern __shared__ char smem[];
    float* bias_s = reinterpret_cast<float*>(smem + BIAS_OFF);

    const int tid = threadIdx.x;
    const int bh = blockIdx.x;   // 0..2  (2 bn tiles each)
    const int bm = blockIdx.y;   // 0..391
    const int bn0 = bh * 2;
    const float s = g_scales[2];

    bias_s[tid] = bias[bh * 256 + tid];
    bias_s[128 + tid] = bias[bh * 256 + 128 + tid];

    const uint32_t a_s = smem_u32(smem + A_OFF);
    const uint32_t b_s = smem_u32(smem + B_OFF);

    // stage A once + B(0) via cp.async
    const uint4* gA = reinterpret_cast<const uint4*>(g_xq + (size_t)bm * 128 * KD);
    const uint4* gB0 = reinterpret_cast<const uint4*>(g_wq + (size_t)bn0 * 128 * KD);
#pragma unroll
    for (int it = 0; it < 24; it++) {
        int cid = tid + it * 128;
        int row = cid / 24, cc = cid % 24;
        uint32_t off = (uint32_t)row * (SSTRIDE * 2) + cc * 16;
        cp16(a_s + off, gA + cid);
        cp16(b_s + off, gB0 + cid);
    }
    cp_commit();
    cp_wait0();
    __syncthreads();

    const int warp = tid >> 5, lane = tid & 31;
    const int wm = warp & 1;   // M sub-tile (64 rows)
    const int wn = warp >> 1;  // N sub-tile (64 cols)

    const uint32_t a_lane_byte =
        (uint32_t)(wm * 64 + (lane & 15)) * (SSTRIDE * 2) + ((lane >> 4) << 4);
    const int grp = lane >> 3;
    const uint32_t b_lane_byte =
        (uint32_t)(wn * 64 + ((grp >> 1) << 3) + (lane & 7)) * (SSTRIDE * 2) +
        ((grp & 1) << 4);
    const int g = lane >> 2, tt = lane & 3;
    const int m_base = bm * 128 + wm * 64;

#pragma unroll 1
    for (int bt = 0; bt < 2; bt++) {
        float acc[4][8][4];
#pragma unroll
        for (int i = 0; i < 4; i++)
#pragma unroll
            for (int j = 0; j < 8; j++)
#pragma unroll
                for (int r = 0; r < 4; r++) acc[i][j][r] = 0.f;

        // fragment double buffers: 4 A + 4 B ldsm.x4 per k-step
        uint32_t afr[2][4][4], bfr[2][4][4];
#pragma unroll
        for (int i = 0; i < 4; i++)
            ldsm4(afr[0][i], a_s + a_lane_byte + (uint32_t)i * (16 * SSTRIDE * 2));
#pragma unroll
        for (int jj = 0; jj < 4; jj++)
            ldsm4(bfr[0][jj], b_s + b_lane_byte + (uint32_t)jj * (16 * SSTRIDE * 2));

#pragma unroll
        for (int ks = 0; ks < 12; ks++) {
            const int cur = ks & 1, nxt = cur ^ 1;
            if (ks < 11) {
                const uint32_t kb = (uint32_t)(ks + 1) * 32;
#pragma unroll
                for (int i = 0; i < 4; i++)
                    ldsm4(afr[nxt][i],
                          a_s + a_lane_byte + (uint32_t)i * (16 * SSTRIDE * 2) + kb);
#pragma unroll
                for (int jj = 0; jj < 4; jj++)
                    ldsm4(bfr[nxt][jj],
                          b_s + b_lane_byte + (uint32_t)jj * (16 * SSTRIDE * 2) + kb);
            }
            // 32 independent MMAs
#pragma unroll
            for (int jj = 0; jj < 4; jj++)
#pragma unroll
                for (int i = 0; i < 4; i++) {
                    mma16816(acc[i][jj * 2],     afr[cur][i],
                             bfr[cur][jj][0], bfr[cur][jj][1]);
                    mma16816(acc[i][jj * 2 + 1], afr[cur][i],
                             bfr[cur][jj][2], bfr[cur][jj][3]);
                }
        }

        // all warps done reading Bs; kick off next B fetch (overlaps epilogue)
        __syncthreads();
        if (bt < 1) {
            const uint4* gB = reinterpret_cast<const uint4*>(
                g_wq + (size_t)(bn0 + 1) * 128 * KD);
#pragma unroll
            for (int it = 0; it < 24; it++) {
                int cid = tid + it * 128;
                int row = cid / 24, cc = cid % 24;
                cp16(b_s + (uint32_t)row * (SSTRIDE * 2) + cc * 16, gB + cid);
            }
            cp_commit();
        }

        // ---- epilogue for this bn tile ----
        const int n_base = (bn0 + bt) * 128 + wn * 64;
        const int l_base = bt * 128 + wn * 64;
#pragma unroll
        for (int i = 0; i < 4; i++) {
            int row0 = m_base + i * 16 + g;
#pragma unroll
            for (int j = 0; j < 8; j++) {
                int col = n_base + j * 8 + tt * 2;
                float2 bv = *reinterpret_cast<const float2*>(
                    &bias_s[l_base + j * 8 + tt * 2]);
                float2 v0 = make_float2(acc[i][j][0] * s + bv.x,
                                        acc[i][j][1] * s + bv.y);
                float2 v1 = make_float2(acc[i][j][2] * s + bv.x,
                                        acc[i][j][3] * s + bv.y);
                *reinterpret_cast<float2*>(&out[(size_t)row0 * D_ + col]) = v0;
                *reinterpret_cast<float2*>(&out[(size_t)(row0 + 8) * D_ + col]) = v1;
            }
        }

        if (bt < 1) {
            cp_wait0();
            __syncthreads();
        }
    }
}

// ===========================================================================
extern "C" void kernel_launch(void* const* d_in, const int* in_sizes, int n_in,
                              void* d_out, int out_size) {
    (void)in_sizes; (void)n_in; (void)out_size;
    const float* x = (const float*)d_in[0];
    const float* w = (const float*)d_in[1];
    const float* b = (const float*)d_in[2];
    float* out = (float*)d_out;

    absmax_kernel<<<PX + PW, 256>>>((const float4*)x, (const float4*)w);
    quant_kernel<<<WQBLOCKS + XQBLOCKS, 256>>>(x, w);

    cudaFuncSetAttribute(gemm_kernel,
                         cudaFuncAttributeMaxDynamicSharedMemorySize, GEMM_SMEM);
    dim3 grid(3, M_ / 128);  // (3, 392)
    gemm_kernel<<<grid, 128, GEMM_SMEM>>>(b, out);
}

// round 17
// speedup vs baseline: 1.0184x; 1.0184x over previous
#include <cuda_runtime.h>
#include <cuda_bf16.h>
#include <cstdint>

// Problem constants
#define B_  64
#define C_  3
#define H_  224
#define W_  224
#define GH  28
#define GW  28
#define D_  768
#define KD  192                 // C*8*8
#define M_  (B_*GH*GW)          // 50176

#define PX 588                  // x: 2408448 float4 / (588*256) = 16 per thread
#define PW 36                   // w: 36864 float4 / (36*256) = 4 per thread

// ---- scratch (no cudaMalloc allowed) ----
__device__ float g_partials[PX + PW];
__device__ float g_scales[3];                              // sx, sw, sx*sw
__device__ int   g_count = 0;                              // self-resetting
__device__ __nv_bfloat16 g_xq[(size_t)M_ * KD];            // 19.3 MB
__device__ __nv_bfloat16 g_wq[(size_t)D_ * KD];            // 288 KB

// ===========================================================================
// Pass 1: per-block absmax partials (16 independent LDG.128 per thread,
// two flights of 8) + fused last-block scale reduction
// ===========================================================================
__device__ __forceinline__ float amax4(float4 v) {
    return fmaxf(fmaxf(fabsf(v.x), fabsf(v.y)), fmaxf(fabsf(v.z), fabsf(v.w)));
}

__global__ void absmax_kernel(const float4* __restrict__ x4,
                              const float4* __restrict__ w4) {
    __shared__ float red[8];
    __shared__ int is_last;
    float m = 0.f;
    if (blockIdx.x < PX) {
        int i = blockIdx.x * 256 + threadIdx.x;
        const int st = PX * 256;
#pragma unroll
        for (int f = 0; f < 2; f++) {
            float4 v0 = x4[i];
            float4 v1 = x4[i + st];
            float4 v2 = x4[i + 2 * st];
            float4 v3 = x4[i + 3 * st];
            float4 v4 = x4[i + 4 * st];
            float4 v5 = x4[i + 5 * st];
            float4 v6 = x4[i + 6 * st];
            float4 v7 = x4[i + 7 * st];
            m = fmaxf(m, fmaxf(
                fmaxf(fmaxf(amax4(v0), amax4(v1)), fmaxf(amax4(v2), amax4(v3))),
                fmaxf(fmaxf(amax4(v4), amax4(v5)), fmaxf(amax4(v6), amax4(v7)))));
            i += 8 * st;
        }
    } else {
        int i = (blockIdx.x - PX) * 256 + threadIdx.x;
        const int st = PW * 256;
        float4 v0 = w4[i];
        float4 v1 = w4[i + st];
        float4 v2 = w4[i + 2 * st];
        float4 v3 = w4[i + 3 * st];
        m = fmaxf(fmaxf(amax4(v0), amax4(v1)), fmaxf(amax4(v2), amax4(v3)));
    }
#pragma unroll
    for (int o = 16; o > 0; o >>= 1)
        m = fmaxf(m, __shfl_xor_sync(0xffffffffu, m, o));
    if ((threadIdx.x & 31) == 0) red[threadIdx.x >> 5] = m;
    __syncthreads();
    if (threadIdx.x < 32) {
        float v = (threadIdx.x < 8) ? red[threadIdx.x] : 0.f;
#pragma unroll
        for (int o = 4; o > 0; o >>= 1)
            v = fmaxf(v, __shfl_xor_sync(0xffffffffu, v, o));
        if (threadIdx.x == 0) {
            g_partials[blockIdx.x] = v;
            __threadfence();
            int c = atomicAdd(&g_count, 1);
            is_last = (c == PX + PW - 1);
        }
    }
    __syncthreads();
    if (!is_last) return;

    float xv = 0.f, wv = 0.f;
    for (int j = threadIdx.x; j < PX; j += 256) xv = fmaxf(xv, g_partials[j]);
    if (threadIdx.x < PW) wv = g_partials[PX + threadIdx.x];
#pragma unroll
    for (int o = 16; o > 0; o >>= 1) {
        xv = fmaxf(xv, __shfl_xor_sync(0xffffffffu, xv, o));
        wv = fmaxf(wv, __shfl_xor_sync(0xffffffffu, wv, o));
    }
    __shared__ float rx[8], rw[8];
    if ((threadIdx.x & 31) == 0) {
        rx[threadIdx.x >> 5] = xv;
        rw[threadIdx.x >> 5] = wv;
    }
    __syncthreads();
    if (threadIdx.x == 0) {
        float a = rx[0], b = rw[0];
#pragma unroll
        for (int j = 1; j < 8; j++) {
            a = fmaxf(a, rx[j]);
            b = fmaxf(b, rw[j]);
        }
        float sx = fmaxf(a, 1e-8f) / 127.0f;
        float sw = fmaxf(b, 1e-8f) / 127.0f;
        g_scales[0] = sx;
        g_scales[1] = sw;
        g_scales[2] = sx * sw;
        g_count = 0;   // reset for next graph replay
    }
}

// ===========================================================================
// Pass 2: quantize w (copy) + x (patchify) -> bf16, one launch, coalesced
// ===========================================================================
__device__ __forceinline__ float fq(float v, float s) {
    return rintf(fminf(fmaxf(v / s, -127.f), 127.f));
}
__device__ __forceinline__ unsigned int pack2(float a, float b, float s) {
    __nv_bfloat162 h = __floats2bfloat162_rn(fq(a, s), fq(b, s));
    return *reinterpret_cast<unsigned int*>(&h);
}

#define WQBLOCKS 144   // 144*256 = 36864 = D_*KD/4
#define XQBLOCKS 4704  // 4704*256 = 1204224 = B_*C_*H_*GW

__global__ void quant_kernel(const float* __restrict__ x,
                             const float* __restrict__ w) {
    int bid = blockIdx.x;
    if (bid < WQBLOCKS) {
        float s = g_scales[1];
        int i = bid * 256 + threadIdx.x;
        float4 v = reinterpret_cast<const float4*>(w)[i];
        uint2 o;
        o.x = pack2(v.x, v.y, s);
        o.y = pack2(v.z, v.w, s);
        reinterpret_cast<uint2*>(g_wq)[i] = o;
    } else {
        float s = g_scales[0];
        int tid = (bid - WQBLOCKS) * 256 + threadIdx.x;
        int wb = tid % GW;
        int h  = (tid / GW) % H_;
        int c  = (tid / (GW * H_)) % C_;
        int b  = tid / (GW * H_ * C_);
        const float4* src = reinterpret_cast<const float4*>(
            x + ((((size_t)b * C_ + c) * H_ + h) * W_ + (size_t)wb * 8));
        float4 v0 = src[0], v1 = src[1];
        int xb = h >> 3, p = h & 7;
        size_t m = (size_t)b * (GH * GW) + (size_t)xb * GW + wb;
        size_t k = (size_t)c * 64 + (size_t)p * 8;
        uint4 o;
        o.x = pack2(v0.x, v0.y, s);
        o.y = pack2(v0.z, v0.w, s);
        o.z = pack2(v1.x, v1.y, s);
        o.w = pack2(v1.z, v1.w, s);
        *reinterpret_cast<uint4*>(g_xq + m * KD + k) = o;
    }
}

// ===========================================================================
// Pass 3: GEMM (R14 config — best measured). 256 threads, 8 warps, warp
// tile 32x64; T=2 bn tiles per CTA, grid (3,392) -> 4 clean waves.
// ldmatrix.x4 + mma.sync m16n8k16, fragment double-buffering; next-B
// cp.async overlaps epilogue.
// ===========================================================================
#define SSTRIDE 200                      // bf16 elems per smem row (400 B)
#define A_OFF   0
#define B_OFF   (128 * SSTRIDE * 2)      // 51200 B
#define BIAS_OFF (2 * 128 * SSTRIDE * 2) // 102400 B
#define GEMM_SMEM (BIAS_OFF + 1024)

__device__ __forceinline__ uint32_t smem_u32(const void* p) {
    uint32_t a;
    asm("{ .reg .u64 t; cvta.to.shared.u64 t, %1; cvt.u32.u64 %0, t; }"
        : "=r"(a) : "l"(p));
    return a;
}
__device__ __forceinline__ void cp16(uint32_t dst, const void* src) {
    asm volatile("cp.async.cg.shared.global [%0], [%1], 16;"
                 :: "r"(dst), "l"(src));
}
__device__ __forceinline__ void cp_commit() {
    asm volatile("cp.async.commit_group;" ::: "memory");
}
__device__ __forceinline__ void cp_wait0() {
    asm volatile("cp.async.wait_group 0;" ::: "memory");
}
__device__ __forceinline__ void ldsm4(uint32_t* r, uint32_t addr) {
    asm volatile("ldmatrix.sync.aligned.m8n8.x4.shared.b16 {%0,%1,%2,%3}, [%4];"
                 : "=r"(r[0]), "=r"(r[1]), "=r"(r[2]), "=r"(r[3]) : "r"(addr));
}
__device__ __forceinline__ void mma16816(float* d, const uint32_t* a,
                                         uint32_t b0, uint32_t b1) {
    asm volatile(
        "mma.sync.aligned.m16n8k16.row.col.f32.bf16.bf16.f32 "
        "{%0,%1,%2,%3}, {%4,%5,%6,%7}, {%8,%9}, {%0,%1,%2,%3};\n"
        : "+f"(d[0]), "+f"(d[1]), "+f"(d[2]), "+f"(d[3])
        : "r"(a[0]), "r"(a[1]), "r"(a[2]), "r"(a[3]), "r"(b0), "r"(b1));
}

__global__ void __launch_bounds__(256, 2)
gemm_kernel(const float* __restrict__ bias, float* __restrict__ out) {
    extern __shared__ char smem[];
    float* bias_s = reinterpret_cast<float*>(smem + BIAS_OFF);

    const int tid = threadIdx.x;
    const int bh = blockIdx.x;   // 0..2  (2 bn tiles each)
    const int bm = blockIdx.y;   // 0..391
    const int bn0 = bh * 2;
    const float s = g_scales[2];

    bias_s[tid] = bias[bh * 256 + tid];

    const uint32_t a_s = smem_u32(smem + A_OFF);
    const uint32_t b_s = smem_u32(smem + B_OFF);

    // stage A once + B(0) via cp.async
    const uint4* gA = reinterpret_cast<const uint4*>(g_xq + (size_t)bm * 128 * KD);
    const uint4* gB0 = reinterpret_cast<const uint4*>(g_wq + (size_t)bn0 * 128 * KD);
#pragma unroll
    for (int it = 0; it < 12; it++) {
        int cid = tid + it * 256;
        int row = cid / 24, cc = cid % 24;
        uint32_t off = (uint32_t)row * (SSTRIDE * 2) + cc * 16;
        cp16(a_s + off, gA + cid);
        cp16(b_s + off, gB0 + cid);
    }
    cp_commit();
    cp_wait0();
    __syncthreads();

    const int warp = tid >> 5, lane = tid & 31;
    const int wm = warp & 3;   // M sub-tile (32 rows)
    const int wn = warp >> 2;  // N sub-tile (64 cols)

    const uint32_t a_lane_byte =
        (uint32_t)(wm * 32 + (lane & 15)) * (SSTRIDE * 2) + ((lane >> 4) << 4);
    const int grp = lane >> 3;
    const uint32_t b_lane_byte =
        (uint32_t)(wn * 64 + ((grp >> 1) << 3) + (lane & 7)) * (SSTRIDE * 2) +
        ((grp & 1) << 4);
    const int g = lane >> 2, tt = lane & 3;
    const int m_base = bm * 128 + wm * 32;

#pragma unroll 1
    for (int bt = 0; bt < 2; bt++) {
        float acc[2][8][4];
#pragma unroll
        for (int i = 0; i < 2; i++)
#pragma unroll
            for (int j = 0; j < 8; j++)
#pragma unroll
                for (int r = 0; r < 4; r++) acc[i][j][r] = 0.f;

        // fragment double buffers
        uint32_t afr[2][2][4], bfr[2][4][4];
#pragma unroll
        for (int i = 0; i < 2; i++)
            ldsm4(afr[0][i], a_s + a_lane_byte + (uint32_t)i * (16 * SSTRIDE * 2));
#pragma unroll
        for (int jj = 0; jj < 4; jj++)
            ldsm4(bfr[0][jj], b_s + b_lane_byte + (uint32_t)jj * (16 * SSTRIDE * 2));

#pragma unroll
        for (int ks = 0; ks < 12; ks++) {
            const int cur = ks & 1, nxt = cur ^ 1;
            if (ks < 11) {
                const uint32_t kb = (uint32_t)(ks + 1) * 32;
#pragma unroll
                for (int i = 0; i < 2; i++)
                    ldsm4(afr[nxt][i],
                          a_s + a_lane_byte + (uint32_t)i * (16 * SSTRIDE * 2) + kb);
#pragma unroll
                for (int jj = 0; jj < 4; jj++)
                    ldsm4(bfr[nxt][jj],
                          b_s + b_lane_byte + (uint32_t)jj * (16 * SSTRIDE * 2) + kb);
            }
#pragma unroll
            for (int jj = 0; jj < 4; jj++)
#pragma unroll
                for (int i = 0; i < 2; i++) {
                    mma16816(acc[i][jj * 2],     afr[cur][i],
                             bfr[cur][jj][0], bfr[cur][jj][1]);
                    mma16816(acc[i][jj * 2 + 1], afr[cur][i],
                             bfr[cur][jj][2], bfr[cur][jj][3]);
                }
        }

        // all warps done reading Bs; kick off next B fetch (overlaps epilogue)
        __syncthreads();
        if (bt < 1) {
            const uint4* gB = reinterpret_cast<const uint4*>(
                g_wq + (size_t)(bn0 + 1) * 128 * KD);
#pragma unroll
            for (int it = 0; it < 12; it++) {
                int cid = tid + it * 256;
                int row = cid / 24, cc = cid % 24;
                cp16(b_s + (uint32_t)row * (SSTRIDE * 2) + cc * 16, gB + cid);
            }
            cp_commit();
        }

        // ---- epilogue for this bn tile ----
        const int n_base = (bn0 + bt) * 128 + wn * 64;
        const int l_base = bt * 128 + wn * 64;
#pragma unroll
        for (int i = 0; i < 2; i++) {
            int row0 = m_base + i * 16 + g;
#pragma unroll
            for (int j = 0; j < 8; j++) {
                int col = n_base + j * 8 + tt * 2;
                float2 bv = *reinterpret_cast<const float2*>(
                    &bias_s[l_base + j * 8 + tt * 2]);
                float2 v0 = make_float2(acc[i][j][0] * s + bv.x,
                                        acc[i][j][1] * s + bv.y);
                float2 v1 = make_float2(acc[i][j][2] * s + bv.x,
                                        acc[i][j][3] * s + bv.y);
                *reinterpret_cast<float2*>(&out[(size_t)row0 * D_ + col]) = v0;
                *reinterpret_cast<float2*>(&out[(size_t)(row0 + 8) * D_ + col]) = v1;
            }
        }

        if (bt < 1) {
            cp_wait0();
            __syncthreads();
        }
    }
}

// ===========================================================================
extern "C" void kernel_launch(void* const* d_in, const int* in_sizes, int n_in,
                              void* d_out, int out_size) {
    (void)in_sizes; (void)n_in; (void)out_size;
    const float* x = (const float*)d_in[0];
    const float* w = (const float*)d_in[1];
    const float* b = (const float*)d_in[2];
    float* out = (float*)d_out;

    absmax_kernel<<<PX + PW, 256>>>((const float4*)x, (const float4*)w);
    quant_kernel<<<WQBLOCKS + XQBLOCKS, 256>>>(x, w);

    cudaFuncSetAttribute(gemm_kernel,
                         cudaFuncAttributeMaxDynamicSharedMemorySize, GEMM_SMEM);
    dim3 grid(3, M_ / 128);  // (3, 392)
    gemm_kernel<<<grid, 256, GEMM_SMEM>>>(b, out);
}